// round 13
// baseline (speedup 1.0000x reference)
#include <cuda_runtime.h>
#include <cuda_bf16.h>
#include <cstdint>

#define MAX_B  32768
#define H      64
#define TPB    256          // 8 warps = 8 batch groups per block

__device__ int g_s32[MAX_B / 32];   // per-32-batch exclusive partials
__device__ int g_t32[MAX_B / 32];
__device__ int g_soff[MAX_B];       // full exclusive offsets
__device__ int g_toff[MAX_B];

// ---------------------------------------------------------------------------
// Kernel 1 (scan-lite): one block, 512 threads; thread i sums elements
// [32i, 32i+32), block-scans the partials, writes per-group exclusive
// prefixes (4 KB).
// ---------------------------------------------------------------------------
__global__ void __launch_bounds__(512)
scan_lite_kernel(const int* __restrict__ size, const int* __restrict__ tsize,
                 int B) {
    __shared__ int sw[16], tw[16];
    const int t = threadIdx.x, lane = t & 31, wid = t >> 5;
    const int ngrp = (B + 31) >> 5;

    int s0 = 0, t0 = 0;
    const int e0 = t * 32;
    if (t < ngrp) {
        #pragma unroll
        for (int j = 0; j < 32; j += 4) {
            if (e0 + j + 3 < B) {
                const int4 a = *(const int4*)(size  + e0 + j);
                const int4 c = *(const int4*)(tsize + e0 + j);
                s0 += a.x + a.y + a.z + a.w;
                t0 += c.x + c.y + c.z + c.w;
            } else {
                for (int k = j; k < 32 && e0 + k < B; k++) {
                    s0 += size[e0 + k]; t0 += tsize[e0 + k];
                }
                break;
            }
        }
    }
    int si = s0, ti = t0;
    #pragma unroll
    for (int o = 1; o < 32; o <<= 1) {
        const int a = __shfl_up_sync(0xffffffffu, si, o);
        const int b = __shfl_up_sync(0xffffffffu, ti, o);
        if (lane >= o) { si += a; ti += b; }
    }
    if (lane == 31) { sw[wid] = si; tw[wid] = ti; }
    __syncthreads();
    if (wid == 0 && lane < 16) {
        int a = sw[lane], b = tw[lane];
        #pragma unroll
        for (int o = 1; o < 16; o <<= 1) {
            const int x = __shfl_up_sync(0xffffu, a, o);
            const int y = __shfl_up_sync(0xffffu, b, o);
            if (lane >= o) { a += x; b += y; }
        }
        sw[lane] = a; tw[lane] = b;
    }
    __syncthreads();
    if (t < ngrp) {
        g_s32[t] = (wid ? sw[wid - 1] : 0) + si - s0;
        g_t32[t] = (wid ? tw[wid - 1] : 0) + ti - t0;
    }
}

// ---------------------------------------------------------------------------
// Kernel 2 (expand): one 32-thread block per 32-batch group; writes the full
// exclusive offsets in parallel across the chip.
// ---------------------------------------------------------------------------
__global__ void __launch_bounds__(32)
expand_kernel(const int* __restrict__ size, const int* __restrict__ tsize,
              int B) {
    const int g    = blockIdx.x;
    const int lane = threadIdx.x;
    const int i    = (g << 5) + lane;
    const int in_range = i < B;
    const int s = in_range ? size[i]  : 0;
    const int t = in_range ? tsize[i] : 0;
    int si = s, ti = t;
    #pragma unroll
    for (int o = 1; o < 32; o <<= 1) {
        const int a = __shfl_up_sync(0xffffffffu, si, o);
        const int c = __shfl_up_sync(0xffffffffu, ti, o);
        if (lane >= o) { si += a; ti += c; }
    }
    if (in_range) {
        g_soff[i] = g_s32[g] + si - s;   // exclusive
        g_toff[i] = g_t32[g] + ti - t;
    }
}

// ---------------------------------------------------------------------------
// helpers
// ---------------------------------------------------------------------------
__device__ __forceinline__ float4 f4add(float4 a, float4 b) {
    return make_float4(a.x + b.x, a.y + b.y, a.z + b.z, a.w + b.w);
}
__device__ __forceinline__ int pick_idx(int ia, int ib, int r) {
    const int v = __shfl_sync(0xffffffffu, ia, r & 31);
    const int w = __shfl_sync(0xffffffffu, ib, r & 31);
    return (r < 32) ? v : w;
}
template <int N>
__device__ __forceinline__ void red16(float (&v)[N]) {
    #pragma unroll
    for (int o = 8; o > 0; o >>= 1) {
        #pragma unroll
        for (int k = 0; k < N; k++)
            v[k] += __shfl_xor_sync(0xffffffffu, v[k], o);
    }
}

// ---------------------------------------------------------------------------
// Kernel 3 (exact round-4 champion body): one warp per batch group;
// 16 lanes/row (quad q), halves h=0/1; item loop = 8 rows / 4 independent
// LDG.128 per lane-pair iteration; serialized 2-per-iter target loop.
// ---------------------------------------------------------------------------
__global__ void __launch_bounds__(TPB)
simplex_kernel(const int*   __restrict__ user,
               const int*   __restrict__ item,
               const int*   __restrict__ tgt,
               const int*   __restrict__ size,
               const int*   __restrict__ tsize,
               const float* __restrict__ uw,
               const float* __restrict__ iw,
               float*       __restrict__ out,
               int B) {
    const int b = blockIdx.x * (TPB >> 5) + (threadIdx.x >> 5);
    if (b >= B) return;
    const int lane = threadIdx.x & 31;
    const int q    = lane & 15;
    const int h    = lane >> 4;

    const int soff = g_soff[b];
    const int toff = g_toff[b];
    const int sz   = size[b];
    const int tsz  = tsize[b];

    // ---- item segment sum: chunks of 64 indices, 8 rows / 4 loads per iter
    float4 acc0 = make_float4(0.f,0.f,0.f,0.f);
    float4 acc1 = make_float4(0.f,0.f,0.f,0.f);
    for (int cb = 0; cb < sz; cb += 64) {
        const int n  = min(sz - cb, 64);
        const int ia = (lane      < n) ? __ldg(&item[soff + cb + lane])      : 0;
        const int ib = (lane + 32 < n) ? __ldg(&item[soff + cb + 32 + lane]) : 0;

        int base = 0;
        for (; base + 8 <= n; base += 8) {
            const int i0 = pick_idx(ia, ib, base + 0 + h);
            const int i1 = pick_idx(ia, ib, base + 2 + h);
            const int i2 = pick_idx(ia, ib, base + 4 + h);
            const int i3 = pick_idx(ia, ib, base + 6 + h);
            const float4 v0 = __ldg((const float4*)&iw[(size_t)i0 * H + 4 * q]);
            const float4 v1 = __ldg((const float4*)&iw[(size_t)i1 * H + 4 * q]);
            const float4 v2 = __ldg((const float4*)&iw[(size_t)i2 * H + 4 * q]);
            const float4 v3 = __ldg((const float4*)&iw[(size_t)i3 * H + 4 * q]);
            acc0 = f4add(acc0, f4add(v0, v2));
            acc1 = f4add(acc1, f4add(v1, v3));
        }
        for (; base < n; base += 2) {
            const int r = base + h;
            if (r < n) {
                const int ii = pick_idx(ia, ib, r);
                acc0 = f4add(acc0, __ldg((const float4*)&iw[(size_t)ii * H + 4 * q]));
            }
        }
    }
    float4 acc = f4add(acc0, acc1);
    acc.x += __shfl_xor_sync(0xffffffffu, acc.x, 16);
    acc.y += __shfl_xor_sync(0xffffffffu, acc.y, 16);
    acc.z += __shfl_xor_sync(0xffffffffu, acc.z, 16);
    acc.w += __shfl_xor_sync(0xffffffffu, acc.w, 16);

    // ---- emb = 0.5*user + 0.5*mean ----
    const int ui   = max(soff + sz - 1, 0);
    const int urow = __ldg(&user[ui]);
    const float4 ue = __ldg((const float4*)&uw[(size_t)urow * H + 4 * q]);
    const float inv = 0.5f / ((float)sz + 1e-6f);
    float4 emb;
    emb.x = 0.5f * ue.x + acc.x * inv;
    emb.y = 0.5f * ue.y + acc.y * inv;
    emb.z = 0.5f * ue.z + acc.z * inv;
    emb.w = 0.5f * ue.w + acc.w * inv;

    // ---- center + L2 normalize (width-16, replicated in both halves) ----
    float v2r[2];
    v2r[0] = emb.x + emb.y + emb.z + emb.w;
    v2r[1] = emb.x*emb.x + emb.y*emb.y + emb.z*emb.z + emb.w*emb.w;
    red16<2>(v2r);
    const float mean = v2r[0] * (1.0f / H);
    const float ss   = fmaxf(v2r[1] - v2r[0] * mean, 0.0f);
    const float invn = 1.0f / fmaxf(sqrtf(ss), 1e-12f);
    float4 en;
    en.x = (emb.x - mean) * invn;
    en.y = (emb.y - mean) * invn;
    en.z = (emb.z - mean) * invn;
    en.w = (emb.w - mean) * invn;

    // ---- targets: two per iteration (one per half). sum(en)==0 so
    //      dot(center(te), en) == dot(te, en). ----
    for (int cb = 0; cb < tsz; cb += 32) {
        const int n  = min(tsz - cb, 32);
        const int ta = (lane < n) ? __ldg(&tgt[toff + cb + lane]) : 0;
        for (int base = 0; base < n; base += 2) {
            const int t = base + h;
            if (t < n) {
                const int row = __shfl_sync(0xffffffffu, ta, t);
                const float4 te = __ldg((const float4*)&iw[(size_t)row * H + 4 * q]);
                float v3[3];
                v3[0] = te.x + te.y + te.z + te.w;
                v3[1] = te.x*te.x + te.y*te.y + te.z*te.z + te.w*te.w;
                v3[2] = te.x*en.x + te.y*en.y + te.z*en.z + te.w*en.w;
                red16<3>(v3);
                if (q == 0) {
                    const float mt  = v3[0] * (1.0f / H);
                    const float sst = fmaxf(v3[1] - v3[0] * mt, 0.0f);
                    out[toff + cb + t] = v3[2] / fmaxf(sqrtf(sst), 1e-12f);
                }
            }
        }
    }
}

// ---------------------------------------------------------------------------
extern "C" void kernel_launch(void* const* d_in, const int* in_sizes, int n_in,
                              void* d_out, int out_size) {
    const int*   user        = (const int*)d_in[0];
    const int*   item        = (const int*)d_in[1];
    const int*   target_item = (const int*)d_in[2];
    const int*   size        = (const int*)d_in[3];
    const int*   target_size = (const int*)d_in[4];
    const float* user_weight = (const float*)d_in[5];
    const float* item_weight = (const float*)d_in[6];
    float*       out         = (float*)d_out;

    const int B    = in_sizes[3];
    const int ngrp = (B + 31) >> 5;
    const int wpb  = TPB >> 5;
    const int grid = (B + wpb - 1) / wpb;

    scan_lite_kernel<<<1, 512>>>(size, target_size, B);
    expand_kernel<<<ngrp, 32>>>(size, target_size, B);
    simplex_kernel<<<grid, TPB>>>(user, item, target_item, size, target_size,
                                  user_weight, item_weight, out, B);
}